// round 13
// baseline (speedup 1.0000x reference)
#include <cuda_runtime.h>

#define CC   64
#define DD   64
#define KK   15
#define KPAD 20
#define KP_INV (1.0f/1.2f)

// [50048][960] stage-A output scratch (rows padded to K2 tile multiple)
__device__ float  g_w[48046080];
__device__ float4 g_spts4[65536];   // (x, y, z, valid)

union F2U { unsigned long long u; float2 f; };

__device__ __forceinline__ void fma2(unsigned long long& acc,
                                     unsigned long long a,
                                     unsigned long long b) {
    asm("fma.rn.f32x2 %0, %1, %2, %0;" : "+l"(acc) : "l"(a), "l"(b));
}
__device__ __forceinline__ unsigned long long mul2(unsigned long long a,
                                                   unsigned long long b) {
    unsigned long long r;
    asm("mul.rn.f32x2 %0, %1, %2;" : "=l"(r) : "l"(a), "l"(b));
    return r;
}
__device__ __forceinline__ unsigned long long dup2(float v) {
    unsigned long long d;
    asm("mov.b64 %0, {%1, %1};" : "=l"(d) : "r"(__float_as_uint(v)));
    return d;
}
__device__ __forceinline__ void cp16(void* smem_dst, const void* gmem_src) {
    unsigned int d = (unsigned int)__cvta_generic_to_shared(smem_dst);
    asm volatile("cp.async.cg.shared.global [%0], [%1], 16;"
                 :: "r"(d), "l"(gmem_src) : "memory");
}

// ---------------------------------------------------------------------------
// K0: g_spts4[m] = (s_pts[m].xyz, rowsum(x[m]) > 0)
// ---------------------------------------------------------------------------
__global__ void prep_kernel(const float* __restrict__ x,
                            const float* __restrict__ s_pts, int M) {
    int row  = blockIdx.x * 8 + (threadIdx.x >> 5);
    int lane = threadIdx.x & 31;
    if (row >= M) return;
    float s = x[row * CC + lane] + x[row * CC + 32 + lane];
    #pragma unroll
    for (int off = 16; off > 0; off >>= 1)
        s += __shfl_xor_sync(0xffffffffu, s, off);
    if (lane == 0) {
        float4 v;
        v.x = s_pts[3*row + 0];
        v.y = s_pts[3*row + 1];
        v.z = s_pts[3*row + 2];
        v.w = (s > 0.0f) ? 1.0f : 0.0f;
        g_spts4[row] = v;
    }
}

// ---------------------------------------------------------------------------
// K1: phase0 + stage A. 8 queries/block, warp owns one query.
//     Writes normalized weighted[n][k*64+c] to g_w.
// ---------------------------------------------------------------------------
__global__ __launch_bounds__(256, 3) void stageA_kernel(
    const float* __restrict__ q_pts,
    const int*   __restrict__ neighb_inds,
    const float* __restrict__ x,
    const float* __restrict__ kernel_points,
    int N)
{
    __shared__ float s_w[8 * 32 * KPAD];   // 20.5 KB
    __shared__ float s_q[24];
    __shared__ float s_kp[45];

    const int tid   = threadIdx.x;
    const int lane  = tid & 31;
    const int qg    = tid >> 5;            // warp id = local query
    const int qbase = blockIdx.x * 8;

    if (tid < 24) {
        int q = tid / 3, p = tid % 3;
        int gq = qbase + q; if (gq >= N) gq = N - 1;
        s_q[tid] = q_pts[gq*3 + p];
    }
    if (tid >= 64 && tid < 64 + KK*3) s_kp[tid - 64] = kernel_points[tid - 64];
    __syncthreads();

    // --- phase 0: lane h computes w row for (q=qg, h=lane) ---
    int gq = qbase + qg; if (gq >= N) gq = N - 1;
    const int my_ind = neighb_inds[gq*32 + lane];
    const float4 sp = __ldg(&g_spts4[my_ind]);
    float cnt = sp.w;
    #pragma unroll
    for (int off = 16; off > 0; off >>= 1)
        cnt += __shfl_xor_sync(0xffffffffu, cnt, off);
    const float inv = 1.0f / fmaxf(cnt, 1.0f);

    {
        const float nx = sp.x - s_q[qg*3 + 0];
        const float ny = sp.y - s_q[qg*3 + 1];
        const float nz = sp.z - s_q[qg*3 + 2];
        float wl[16];
        #pragma unroll
        for (int k = 0; k < KK; k++) {
            float dx = nx - s_kp[k*3 + 0];
            float dy = ny - s_kp[k*3 + 1];
            float dz = nz - s_kp[k*3 + 2];
            wl[k] = fmaxf(1.0f - sqrtf(dx*dx + dy*dy + dz*dz) * KP_INV, 0.0f);
        }
        wl[15] = 0.0f;
        float4* wrow = (float4*)(s_w + tid * KPAD);   // stride 80B: conflict deg 4
        wrow[0] = make_float4(wl[0],  wl[1],  wl[2],  wl[3]);
        wrow[1] = make_float4(wl[4],  wl[5],  wl[6],  wl[7]);
        wrow[2] = make_float4(wl[8],  wl[9],  wl[10], wl[11]);
        wrow[3] = make_float4(wl[12], wl[13], wl[14], wl[15]);
    }
    __syncthreads();

    // --- stage A (FFMA2, k-pair packed): thread = channels (2*lane, 2*lane+1) ---
    unsigned long long acc[2][8];
    #pragma unroll
    for (int ci = 0; ci < 2; ci++)
        #pragma unroll
        for (int kp = 0; kp < 8; kp++) acc[ci][kp] = 0ull;

    #pragma unroll 4
    for (int h = 0; h < 32; h++) {
        const int ind = __shfl_sync(0xffffffffu, my_ind, h);
        const float2 f = __ldg((const float2*)(x + ind*CC) + lane);
        const unsigned long long fda = dup2(f.x);
        const unsigned long long fdb = dup2(f.y);
        const ulonglong2* wp = (const ulonglong2*)(s_w + (qg*32 + h)*KPAD);
        const ulonglong2 wA = wp[0], wB = wp[1], wC = wp[2], wD = wp[3];
        fma2(acc[0][0], wA.x, fda);  fma2(acc[1][0], wA.x, fdb);
        fma2(acc[0][1], wA.y, fda);  fma2(acc[1][1], wA.y, fdb);
        fma2(acc[0][2], wB.x, fda);  fma2(acc[1][2], wB.x, fdb);
        fma2(acc[0][3], wB.y, fda);  fma2(acc[1][3], wB.y, fdb);
        fma2(acc[0][4], wC.x, fda);  fma2(acc[1][4], wC.x, fdb);
        fma2(acc[0][5], wC.y, fda);  fma2(acc[1][5], wC.y, fdb);
        fma2(acc[0][6], wD.x, fda);  fma2(acc[1][6], wD.x, fdb);
        fma2(acc[0][7], wD.y, fda);  fma2(acc[1][7], wD.y, fdb);
    }

    // --- normalize + store to g_w[n][k*64 + c] ---
    if (qbase + qg < N) {
        const unsigned long long iv = dup2(inv);
        float* base = g_w + (qbase + qg)*960 + 2*lane;
        #pragma unroll
        for (int kp = 0; kp < 8; kp++) {
            F2U a0; a0.u = mul2(acc[0][kp], iv);
            F2U a1; a1.u = mul2(acc[1][kp], iv);
            *(float2*)(base + (2*kp)*CC)   = make_float2(a0.f.x, a1.f.x);
            if (kp < 7)
                *(float2*)(base + (2*kp+1)*CC) = make_float2(a0.f.y, a1.f.y);
        }
    }
}

// ---------------------------------------------------------------------------
// K2: out[N x 64] = g_w[N x 960] @ weights[960 x 64], FFMA2, cp.async pipeline.
//     128-row tiles, thread = 8 rows x 4 cols.
// ---------------------------------------------------------------------------
__global__ __launch_bounds__(256, 3) void gemm_kernel(
    const float* __restrict__ weights,
    float*       __restrict__ out,
    int N)
{
    __shared__ float s_A[2][128*16];   // 16 KB
    __shared__ float s_W[2][16*64];    //  8 KB

    const int tid = threadIdx.x;
    const int td  = tid & 15;          // 4 output cols: td*4..+3
    const int tn  = tid >> 4;          // 8 output rows: 8*tn..+7
    const int n0  = blockIdx.x * 128;

    unsigned long long o[8][2];
    #pragma unroll
    for (int i = 0; i < 8; i++) { o[i][0] = 0ull; o[i][1] = 0ull; }

    // chunk loader: A[128][16] + W[16][64] for kc0
    const int a_row0 = (tid*2)   >> 2, a_j0 = (tid*2)   & 3;
    const int a_row1 = (tid*2+1) >> 2, a_j1 = (tid*2+1) & 3;
    const int w_kc   = tid >> 4,       w_d4 = tid & 15;

    #define LOAD_CHUNK(buf, kc0) do {                                          \
        cp16(&s_A[buf][a_row0*16 + a_j0*4],                                    \
             g_w + (unsigned long long)(n0 + a_row0)*960 + (kc0) + a_j0*4);    \
        cp16(&s_A[buf][a_row1*16 + a_j1*4],                                    \
             g_w + (unsigned long long)(n0 + a_row1)*960 + (kc0) + a_j1*4);    \
        cp16(&s_W[buf][w_kc*64 + w_d4*4],                                      \
             weights + ((kc0) + w_kc)*64 + w_d4*4);                            \
        asm volatile("cp.async.commit_group;" ::: "memory");                   \
    } while (0)

    LOAD_CHUNK(0, 0);

    for (int it = 0; it < 60; it++) {
        const int cur = it & 1;
        if (it < 59) {
            LOAD_CHUNK(cur ^ 1, (it + 1) * 16);
            asm volatile("cp.async.wait_group 1;" ::: "memory");
        } else {
            asm volatile("cp.async.wait_group 0;" ::: "memory");
        }
        __syncthreads();

        const float* A  = s_A[cur];
        const float* Wm = s_W[cur];
        #pragma unroll
        for (int kcg = 0; kcg < 4; kcg++) {
            ulonglong2 wk[4];
            #pragma unroll
            for (int j = 0; j < 4; j++)
                wk[j] = *(const ulonglong2*)(Wm + (kcg*4 + j)*64 + td*4);
            #pragma unroll
            for (int i = 0; i < 8; i++) {
                const float4 a4 = *(const float4*)(A + (8*tn + i)*16 + kcg*4);
                unsigned long long vd;
                vd = dup2(a4.x); fma2(o[i][0], wk[0].x, vd); fma2(o[i][1], wk[0].y, vd);
                vd = dup2(a4.y); fma2(o[i][0], wk[1].x, vd); fma2(o[i][1], wk[1].y, vd);
                vd = dup2(a4.z); fma2(o[i][0], wk[2].x, vd); fma2(o[i][1], wk[2].y, vd);
                vd = dup2(a4.w); fma2(o[i][0], wk[3].x, vd); fma2(o[i][1], wk[3].y, vd);
            }
        }
        __syncthreads();
    }
    #undef LOAD_CHUNK

    #pragma unroll
    for (int i = 0; i < 8; i++) {
        const int n = n0 + 8*tn + i;
        if (n < N) {
            F2U p0; p0.u = o[i][0];
            F2U p1; p1.u = o[i][1];
            *(float4*)(out + n*DD + td*4) =
                make_float4(p0.f.x, p0.f.y, p1.f.x, p1.f.y);
        }
    }
}

// ---------------------------------------------------------------------------
extern "C" void kernel_launch(void* const* d_in, const int* in_sizes, int n_in,
                              void* d_out, int out_size) {
    const float* q_pts         = (const float*)d_in[0];
    const float* s_pts         = (const float*)d_in[1];
    const int*   neighb_inds   = (const int*)  d_in[2];
    const float* x             = (const float*)d_in[3];
    const float* kernel_points = (const float*)d_in[4];
    const float* weights       = (const float*)d_in[5];
    float*       out           = (float*)d_out;

    const int N = in_sizes[0] / 3;
    const int M = in_sizes[1] / 3;

    prep_kernel  <<<(M + 7) / 8, 256>>>(x, s_pts, M);
    stageA_kernel<<<(N + 7) / 8, 256>>>(q_pts, neighb_inds, x, kernel_points, N);
    gemm_kernel  <<<(N + 127) / 128, 256>>>(weights, out, N);
}